// round 9
// baseline (speedup 1.0000x reference)
#include <cuda_runtime.h>

#define N_ANCH 262144
#define N_CLS 80
#define KTOP 1024
#define CAP 6000
#define FULLM 0xffffffffu

// ---------------- device scratch (zero-initialized at load; reset at end-of-use) ----
__device__ __align__(16) unsigned g_key[N_ANCH];
__device__ unsigned char       g_label[N_ANCH];
__device__ unsigned            g_hist0[2048], g_hist1[2048];
__device__ unsigned            g_done0, g_done1, g_done3, g_done4;
__device__ unsigned            g_sel1, g_need1, g_thresh;
__device__ unsigned            g_ncand, g_maxc;
__device__ unsigned long long  g_cand[CAP];
__device__ unsigned long long  g_sorted[KTOP];
__device__ float4              g_box[KTOP];
__device__ float               g_conf[KTOP], g_labf[KTOP];
__device__ unsigned            g_mask[KTOP * 32];
__device__ unsigned char       g_rownz[KTOP];

__device__ __forceinline__ unsigned fkey(float f) {
    unsigned u = __float_as_uint(f);
    return (u & 0x80000000u) ? ~u : (u | 0x80000000u);
}
__device__ __forceinline__ void pdl_wait()    { asm volatile("griddepcontrol.wait;" ::: "memory"); }
__device__ __forceinline__ void pdl_trigger() { asm volatile("griddepcontrol.launch_dependents;" ::: "memory"); }

// Suffix-scan a 2048-bin histogram (256 threads); find the bin where the
// suffix-count crosses `need`. pass0 -> (g_sel1,g_need1); pass1 -> g_thresh.
__device__ __forceinline__ void scan_pick(const unsigned* hist, unsigned need,
                                          unsigned* cA, unsigned* cB, int pass, unsigned sel1) {
    int tid = threadIdx.x;
    unsigned v[8]; unsigned s = 0;
#pragma unroll
    for (int k = 0; k < 8; k++) { v[k] = __ldcg(&hist[tid * 8 + k]); s += v[k]; }
    cA[tid] = s;
    __syncthreads();
    unsigned* a = cA; unsigned* b = cB;
    for (int off = 1; off < 256; off <<= 1) {
        unsigned x = a[tid] + ((tid + off < 256) ? a[tid + off] : 0u);
        b[tid] = x;
        __syncthreads();
        unsigned* t = a; a = b; b = t;
    }
    unsigned Cexcl = (tid + 1 < 256) ? a[tid + 1] : 0u;
    unsigned Sincl[8];
    unsigned run = Cexcl;
    for (int k = 7; k >= 0; k--) { run += v[k]; Sincl[k] = run; }
#pragma unroll
    for (int k = 0; k < 8; k++) {
        unsigned Sx = (k < 7) ? Sincl[k + 1] : Cexcl;
        if (Sx < need && need <= Sincl[k]) {
            unsigned bin = (unsigned)(tid * 8 + k);
            if (pass == 0) { g_sel1 = bin; g_need1 = need - Sx; }
            else           { g_thresh = (sel1 << 21) | (bin << 10); }
        }
    }
}

// ---------------- kernel 1: conf/argmax + fused hist pass 0 ----------------
__global__ void __launch_bounds__(256) conf_kernel(const float* __restrict__ scores) {
    __shared__ unsigned sh[2048];
    __shared__ unsigned cA[256], cB[256];
    __shared__ int lastFlag;
    int tid = threadIdx.x, lane = tid & 31;
    for (int i = tid; i < 2048; i += 256) sh[i] = 0u;

    int gw = (int)((blockIdx.x * 256u + tid) >> 5);
    int g = lane >> 2, c = lane & 3;
    int anchor = gw * 8 + g;
    const float4* p = (const float4*)scores + (size_t)anchor * 20;
    float4 f0 = __ldg(p + c);
    float4 f1 = __ldg(p + c + 4);
    float4 f2 = __ldg(p + c + 8);
    float4 f3 = __ldg(p + c + 12);
    float4 f4 = __ldg(p + c + 16);

    unsigned long long best = 0ull;
#define UPD(val, idx) { unsigned long long k64 = ((unsigned long long)__float_as_uint(val) << 32) \
                                               | (unsigned)(~(unsigned)(idx)); if (k64 > best) best = k64; }
    int b0 = 4 * c;
    UPD(f0.x, b0 + 0)  UPD(f0.y, b0 + 1)  UPD(f0.z, b0 + 2)  UPD(f0.w, b0 + 3)
    UPD(f1.x, b0 + 16) UPD(f1.y, b0 + 17) UPD(f1.z, b0 + 18) UPD(f1.w, b0 + 19)
    UPD(f2.x, b0 + 32) UPD(f2.y, b0 + 33) UPD(f2.z, b0 + 34) UPD(f2.w, b0 + 35)
    UPD(f3.x, b0 + 48) UPD(f3.y, b0 + 49) UPD(f3.z, b0 + 50) UPD(f3.w, b0 + 51)
    UPD(f4.x, b0 + 64) UPD(f4.y, b0 + 65) UPD(f4.z, b0 + 66) UPD(f4.w, b0 + 67)
#undef UPD
    unsigned long long o;
    o = __shfl_xor_sync(FULLM, best, 1); if (o > best) best = o;
    o = __shfl_xor_sync(FULLM, best, 2); if (o > best) best = o;

    unsigned key = 0;
    bool act = (c == 0);
    if (act) {
        unsigned bits = (unsigned)(best >> 32);
        unsigned label = ~(unsigned)(best & 0xffffffffull);
        float conf = __uint_as_float(bits);
        float mk = (conf >= 0.5f) ? conf : -1.0f;
        key = fkey(mk);
        g_key[anchor] = key;
        g_label[anchor] = (unsigned char)label;
    }
    unsigned am = __ballot_sync(FULLM, act);
    if (act) {
        unsigned d = key >> 21;
        unsigned peers = __match_any_sync(am, d);
        if ((unsigned)(__ffs(peers) - 1) == (unsigned)lane) atomicAdd(&sh[d], __popc(peers));
    }
    __syncthreads();
    for (int i = tid; i < 2048; i += 256)
        if (sh[i]) atomicAdd(&g_hist0[i], sh[i]);
    __threadfence();
    if (tid == 0) lastFlag = (atomicAdd(&g_done0, 1u) == gridDim.x - 1);
    __syncthreads();
    if (!lastFlag) { pdl_trigger(); return; }

    scan_pick(g_hist0, KTOP, cA, cB, 0, 0);
    __syncthreads();
    for (int i = tid; i < 2048; i += 256) g_hist0[i] = 0u;
    if (tid == 0) g_done0 = 0u;
    __threadfence();
    pdl_trigger();
}

// ---------------- kernel 2: radix pass 1 -> threshold ----------------
__global__ void __launch_bounds__(256) hist_kernel() {
    __shared__ unsigned sh[2048];
    __shared__ unsigned cA[256], cB[256];
    __shared__ int lastFlag;
    int tid = threadIdx.x, lane = tid & 31;
    for (int i = tid; i < 2048; i += 256) sh[i] = 0u;
    __syncthreads();
    pdl_wait();
    unsigned sel1 = g_sel1;

    int base = (int)(blockIdx.x * 256u + tid) * 4;
    uint4 kv = *(const uint4*)&g_key[base];
    unsigned ks[4] = {kv.x, kv.y, kv.z, kv.w};
#pragma unroll
    for (int e = 0; e < 4; e++) {
        unsigned k = ks[e];
        bool act = ((k >> 21) == sel1);
        unsigned d = (k >> 10) & 2047u;
        unsigned am = __ballot_sync(FULLM, act);
        if (act) {
            unsigned peers = __match_any_sync(am, d);
            if ((unsigned)(__ffs(peers) - 1) == (unsigned)lane) atomicAdd(&sh[d], __popc(peers));
        }
    }
    __syncthreads();
    for (int i = tid; i < 2048; i += 256)
        if (sh[i]) atomicAdd(&g_hist1[i], sh[i]);
    __threadfence();
    if (tid == 0) lastFlag = (atomicAdd(&g_done1, 1u) == gridDim.x - 1);
    __syncthreads();
    if (!lastFlag) { pdl_trigger(); return; }

    scan_pick(g_hist1, g_need1, cA, cB, 1, sel1);
    __syncthreads();
    for (int i = tid; i < 2048; i += 256) g_hist1[i] = 0u;
    if (tid == 0) g_done1 = 0u;
    __threadfence();
    pdl_trigger();
}

// ---------------- kernel 3: compact candidates with key >= thresh ----------------
__global__ void __launch_bounds__(256) compact_kernel() {
    pdl_wait();
    unsigned T = g_thresh;
    int lane = threadIdx.x & 31;
    int base = (int)(blockIdx.x * 256u + threadIdx.x) * 4;
    uint4 kv = *(const uint4*)&g_key[base];
    unsigned ks[4] = {kv.x, kv.y, kv.z, kv.w};
#pragma unroll
    for (int e = 0; e < 4; e++) {
        unsigned k = ks[e];
        bool sel = (k >= T);
        unsigned m = __ballot_sync(FULLM, sel);
        if (!m) continue;
        unsigned pos0;
        if (lane == 0) pos0 = atomicAdd(&g_ncand, __popc(m));
        pos0 = __shfl_sync(FULLM, pos0, 0);
        if (sel) {
            unsigned pos = pos0 + __popc(m & ((1u << lane) - 1u));
            if (pos < CAP)
                g_cand[pos] = (((unsigned long long)k) << 32) | (unsigned)(~(unsigned)(base + e));
        }
    }
    __threadfence();
    pdl_trigger();
}

// ---------------- kernel 4: rank (brute force) + prep in last block --------------
__global__ void __launch_bounds__(1024) rank_kernel(const float* __restrict__ boxes) {
    __shared__ unsigned long long buf[CAP];     // 48000 B
    __shared__ int lastFlag;
    int tid = threadIdx.x;
    pdl_wait();
    unsigned nc = __ldcg(&g_ncand);
    if (nc > CAP) nc = CAP;
    int i = (int)(blockIdx.x * 1024u) + tid;

    if (blockIdx.x * 1024u < nc) {
        for (unsigned j = tid; j < nc; j += 1024u) buf[j] = __ldcg(&g_cand[j]);
        __syncthreads();
        if (i < (int)nc) {
            unsigned long long my = buf[i];
            unsigned r = 0;
            for (unsigned j = 0; j < nc; j++) r += (buf[j] > my) ? 1u : 0u;
            if (r < KTOP) g_sorted[r] = my;
        }
    }
    __threadfence();
    if (tid == 0) lastFlag = (atomicAdd(&g_done3, 1u) == gridDim.x - 1);
    __syncthreads();
    if (!lastFlag) { pdl_trigger(); return; }

    {   // prep: decode, gather boxes, global max coordinate
        int r = tid;
        unsigned long long s = __ldcg(&g_sorted[r]);
        unsigned idx = ~(unsigned)(s & 0xffffffffull);
        unsigned kb = (unsigned)(s >> 32);
        unsigned fb = (kb & 0x80000000u) ? (kb & 0x7fffffffu) : ~kb;
        float4 bx = __ldg((const float4*)boxes + idx);
        g_box[r] = bx;
        g_conf[r] = __uint_as_float(fb);
        g_labf[r] = (float)(unsigned)g_label[idx];
        float m = fmaxf(fmaxf(bx.x, bx.y), fmaxf(bx.z, bx.w));
        atomicMax(&g_maxc, __float_as_uint(m));   // coords >= 0 -> bit-monotone
    }
    if (tid == 0) { g_done3 = 0u; g_ncand = 0u; }
    __threadfence();
    pdl_trigger();
}

// ---------------- kernel 5: IoU mask + final NMS in last block -------------------
__global__ void __launch_bounds__(256) mask_kernel(float* __restrict__ out) {
    __shared__ float4 sobox[KTOP];              // 16 KB
    __shared__ int lastFlag;
    __shared__ unsigned keepw[32], nzm[32];
    __shared__ unsigned short list[KTOP];
    __shared__ int Lsh;
    int tid = threadIdx.x, lane = tid & 31, warp = tid >> 5;

    pdl_wait();
    float mc = __uint_as_float(__ldcg(&g_maxc)) + 1.0f;   // max(top_boxes)+1
    for (int j = tid; j < KTOP; j += 256) {
        float4 b = __ldcg(&g_box[j]);
        float off = __ldcg(&g_labf[j]) * mc;
        sobox[j] = make_float4(b.x + off, b.y + off, b.z + off, b.w + off);
    }
    __syncthreads();

    int row = (int)blockIdx.x * 8 + warp;
    float4 bi = sobox[row];
    float ai = (bi.z - bi.x) * (bi.w - bi.y);
    unsigned rowor = 0;
#pragma unroll 4
    for (int it = 0; it < 32; it++) {
        int j = it * 32 + lane;
        float4 bj = sobox[j];
        float aj = (bj.z - bj.x) * (bj.w - bj.y);
        float lx = fmaxf(bi.x, bj.x), ly = fmaxf(bi.y, bj.y);
        float rx = fminf(bi.z, bj.z), ry = fminf(bi.w, bj.w);
        float w = fmaxf(rx - lx, 0.0f), h = fmaxf(ry - ly, 0.0f);
        float inter = w * h;
        float uni = ai + aj - inter;
        float iou = inter / fmaxf(uni, 1e-9f);
        bool sup = (iou > 0.6f) && (j > row);
        unsigned bal = __ballot_sync(FULLM, sup);
        if (lane == 0) g_mask[row * 32 + it] = bal;
        rowor |= bal;
    }
    if (lane == 0) g_rownz[row] = (rowor != 0u) ? 1 : 0;

    __threadfence();
    if (tid == 0) lastFlag = (atomicAdd(&g_done4, 1u) == gridDim.x - 1);
    __syncthreads();
    if (!lastFlag) { pdl_trigger(); return; }

    // final: sparse greedy NMS + masked output
    for (int w = warp; w < 32; w += 8) {
        float c = __ldcg(&g_conf[w * 32 + lane]);
        unsigned b = __ballot_sync(FULLM, c >= 0.5f);
        if (lane == 0) keepw[w] = b;
    }
    for (int w = warp; w < 32; w += 8) {
        unsigned char z = __ldcg(&g_rownz[w * 32 + lane]);
        unsigned b = __ballot_sync(FULLM, z != 0);
        if (lane == 0) nzm[w] = b;
    }
    __syncthreads();
    if (tid == 0) {
        int L = 0;
        for (int w = 0; w < 32; w++) {
            unsigned m = nzm[w];
            while (m) { int b = __ffs(m) - 1; list[L++] = (unsigned short)(w * 32 + b); m &= m - 1; }
        }
        Lsh = L;
    }
    __syncthreads();
    if (warp == 0) {
        unsigned kw = keepw[lane];
        int L = Lsh;
        for (int t = 0; t < L; t++) {
            int i = list[t];
            unsigned ow = __shfl_sync(FULLM, kw, i >> 5);
            if ((ow >> (i & 31)) & 1u) kw &= ~__ldcg(&g_mask[i * 32 + lane]);
        }
        keepw[lane] = kw;
    }
    __syncthreads();
    for (int r = tid; r < KTOP; r += 256) {
        bool kp = (keepw[r >> 5] >> (r & 31)) & 1u;
        float4 b = __ldcg(&g_box[r]);
        float c = __ldcg(&g_conf[r]);
        float lf = __ldcg(&g_labf[r]);
        float* o = out + r * 6;
        if (kp) { o[0] = b.x; o[1] = b.y; o[2] = b.z; o[3] = b.w; o[4] = c; o[5] = lf; }
        else    { o[0] = 0.f; o[1] = 0.f; o[2] = 0.f; o[3] = 0.f; o[4] = 0.f; o[5] = 0.f; }
    }
    if (tid == 0) { g_done4 = 0u; g_maxc = 0u; }
    __threadfence();
    pdl_trigger();
}

// ------- launch: PDL attribute, with plain-launch fallback if rejected -----------
// griddepcontrol.{wait,launch_dependents} are no-ops without PDL, and plain
// stream order provides the same dependency chain, so the fallback is correct.
template <typename K, typename... Args>
static inline void launch_pdl(K kern, dim3 grid, dim3 block, Args... args) {
    cudaLaunchAttribute attr[1];
    attr[0].id = cudaLaunchAttributeProgrammaticStreamSerialization;
    attr[0].val.programmaticStreamSerializationAllowed = 1;
    cudaLaunchConfig_t cfg = {};
    cfg.gridDim = grid;
    cfg.blockDim = block;
    cfg.dynamicSmemBytes = 0;
    cfg.stream = 0;
    cfg.attrs = attr;
    cfg.numAttrs = 1;
    cudaError_t err = cudaLaunchKernelEx(&cfg, kern, args...);
    if (err != cudaSuccess) {
        (void)cudaGetLastError();          // clear sticky-free error state
        kern<<<grid, block>>>(args...);    // plain launch: stream order = same deps
    }
}

extern "C" void kernel_launch(void* const* d_in, const int* in_sizes, int n_in,
                              void* d_out, int out_size) {
    const float* boxes  = (const float*)d_in[0];
    const float* scores = (const float*)d_in[1];
    if (n_in >= 2 && in_sizes[0] > in_sizes[1]) { const float* t = boxes; boxes = scores; scores = t; }

    launch_pdl(conf_kernel,    dim3(N_ANCH / 64),   dim3(256), scores);
    launch_pdl(hist_kernel,    dim3(N_ANCH / 1024), dim3(256));
    launch_pdl(compact_kernel, dim3(N_ANCH / 1024), dim3(256));
    launch_pdl(rank_kernel,    dim3(6),             dim3(1024), boxes);
    launch_pdl(mask_kernel,    dim3(KTOP / 8),      dim3(256), (float*)d_out);
}

// round 12
// speedup vs baseline: 1.1945x; 1.1945x over previous
#include <cuda_runtime.h>

#define N_ANCH 262144
#define N_CLS 80
#define KTOP 1024
#define CAP 6000
#define RTHR 128
#define RBLK 48
#define FULLM 0xffffffffu

// ---------------- device scratch (zero-initialized at load; reset at end-of-use) ----
__device__ __align__(16) unsigned g_key[N_ANCH];
__device__ unsigned char       g_label[N_ANCH];
__device__ unsigned            g_hist0[2048], g_hist1[2048];
__device__ unsigned            g_done0, g_done1, g_done3, g_done4;
__device__ unsigned            g_sel1, g_need1, g_thresh;
__device__ unsigned            g_ncand, g_maxc;
__device__ __align__(16) unsigned long long g_cand[CAP];
__device__ unsigned long long  g_sorted[KTOP];
__device__ float4              g_box[KTOP];
__device__ float               g_conf[KTOP], g_labf[KTOP];
__device__ unsigned            g_mask[KTOP * 32];
__device__ unsigned char       g_rownz[KTOP];

__device__ __forceinline__ unsigned fkey(float f) {
    unsigned u = __float_as_uint(f);
    return (u & 0x80000000u) ? ~u : (u | 0x80000000u);
}
__device__ __forceinline__ void pdl_wait()    { asm volatile("griddepcontrol.wait;" ::: "memory"); }
__device__ __forceinline__ void pdl_trigger() { asm volatile("griddepcontrol.launch_dependents;" ::: "memory"); }

// Suffix-scan a 2048-bin histogram (256 threads); find the bin where the
// suffix-count crosses `need`. pass0 -> (g_sel1,g_need1); pass1 -> g_thresh.
__device__ __forceinline__ void scan_pick(const unsigned* hist, unsigned need,
                                          unsigned* cA, unsigned* cB, int pass, unsigned sel1) {
    int tid = threadIdx.x;
    unsigned v[8]; unsigned s = 0;
#pragma unroll
    for (int k = 0; k < 8; k++) { v[k] = __ldcg(&hist[tid * 8 + k]); s += v[k]; }
    cA[tid] = s;
    __syncthreads();
    unsigned* a = cA; unsigned* b = cB;
    for (int off = 1; off < 256; off <<= 1) {
        unsigned x = a[tid] + ((tid + off < 256) ? a[tid + off] : 0u);
        b[tid] = x;
        __syncthreads();
        unsigned* t = a; a = b; b = t;
    }
    unsigned Cexcl = (tid + 1 < 256) ? a[tid + 1] : 0u;
    unsigned Sincl[8];
    unsigned run = Cexcl;
    for (int k = 7; k >= 0; k--) { run += v[k]; Sincl[k] = run; }
#pragma unroll
    for (int k = 0; k < 8; k++) {
        unsigned Sx = (k < 7) ? Sincl[k + 1] : Cexcl;
        if (Sx < need && need <= Sincl[k]) {
            unsigned bin = (unsigned)(tid * 8 + k);
            if (pass == 0) { g_sel1 = bin; g_need1 = need - Sx; }
            else           { g_thresh = (sel1 << 21) | (bin << 10); }
        }
    }
}

// ---------------- kernel 1: conf/argmax + fused hist pass 0 ----------------
__global__ void __launch_bounds__(256) conf_kernel(const float* __restrict__ scores) {
    __shared__ unsigned sh[2048];
    __shared__ unsigned cA[256], cB[256];
    __shared__ int lastFlag;
    int tid = threadIdx.x, lane = tid & 31;
    for (int i = tid; i < 2048; i += 256) sh[i] = 0u;

    int gw = (int)((blockIdx.x * 256u + tid) >> 5);
    int g = lane >> 2, c = lane & 3;
    int anchor = gw * 8 + g;
    const float4* p = (const float4*)scores + (size_t)anchor * 20;
    float4 f0 = __ldg(p + c);
    float4 f1 = __ldg(p + c + 4);
    float4 f2 = __ldg(p + c + 8);
    float4 f3 = __ldg(p + c + 12);
    float4 f4 = __ldg(p + c + 16);

    unsigned long long best = 0ull;
#define UPD(val, idx) { unsigned long long k64 = ((unsigned long long)__float_as_uint(val) << 32) \
                                               | (unsigned)(~(unsigned)(idx)); if (k64 > best) best = k64; }
    int b0 = 4 * c;
    UPD(f0.x, b0 + 0)  UPD(f0.y, b0 + 1)  UPD(f0.z, b0 + 2)  UPD(f0.w, b0 + 3)
    UPD(f1.x, b0 + 16) UPD(f1.y, b0 + 17) UPD(f1.z, b0 + 18) UPD(f1.w, b0 + 19)
    UPD(f2.x, b0 + 32) UPD(f2.y, b0 + 33) UPD(f2.z, b0 + 34) UPD(f2.w, b0 + 35)
    UPD(f3.x, b0 + 48) UPD(f3.y, b0 + 49) UPD(f3.z, b0 + 50) UPD(f3.w, b0 + 51)
    UPD(f4.x, b0 + 64) UPD(f4.y, b0 + 65) UPD(f4.z, b0 + 66) UPD(f4.w, b0 + 67)
#undef UPD
    unsigned long long o;
    o = __shfl_xor_sync(FULLM, best, 1); if (o > best) best = o;
    o = __shfl_xor_sync(FULLM, best, 2); if (o > best) best = o;

    unsigned key = 0;
    bool act = (c == 0);
    if (act) {
        unsigned bits = (unsigned)(best >> 32);
        unsigned label = ~(unsigned)(best & 0xffffffffull);
        float conf = __uint_as_float(bits);
        float mk = (conf >= 0.5f) ? conf : -1.0f;
        key = fkey(mk);
        g_key[anchor] = key;
        g_label[anchor] = (unsigned char)label;
    }
    unsigned am = __ballot_sync(FULLM, act);
    if (act) {
        unsigned d = key >> 21;
        unsigned peers = __match_any_sync(am, d);
        if ((unsigned)(__ffs(peers) - 1) == (unsigned)lane) atomicAdd(&sh[d], __popc(peers));
    }
    __syncthreads();
    for (int i = tid; i < 2048; i += 256)
        if (sh[i]) atomicAdd(&g_hist0[i], sh[i]);
    __threadfence();
    if (tid == 0) lastFlag = (atomicAdd(&g_done0, 1u) == gridDim.x - 1);
    __syncthreads();
    if (!lastFlag) { pdl_trigger(); return; }

    scan_pick(g_hist0, KTOP, cA, cB, 0, 0);
    __syncthreads();
    for (int i = tid; i < 2048; i += 256) g_hist0[i] = 0u;
    if (tid == 0) g_done0 = 0u;
    __threadfence();
    pdl_trigger();
}

// ---------------- kernel 2: radix pass 1 -> threshold ----------------
__global__ void __launch_bounds__(256) hist_kernel() {
    __shared__ unsigned sh[2048];
    __shared__ unsigned cA[256], cB[256];
    __shared__ int lastFlag;
    int tid = threadIdx.x, lane = tid & 31;
    for (int i = tid; i < 2048; i += 256) sh[i] = 0u;
    __syncthreads();
    pdl_wait();
    unsigned sel1 = g_sel1;

    int base = (int)(blockIdx.x * 256u + tid) * 4;
    uint4 kv = *(const uint4*)&g_key[base];
    unsigned ks[4] = {kv.x, kv.y, kv.z, kv.w};
#pragma unroll
    for (int e = 0; e < 4; e++) {
        unsigned k = ks[e];
        bool act = ((k >> 21) == sel1);
        unsigned d = (k >> 10) & 2047u;
        unsigned am = __ballot_sync(FULLM, act);
        if (act) {
            unsigned peers = __match_any_sync(am, d);
            if ((unsigned)(__ffs(peers) - 1) == (unsigned)lane) atomicAdd(&sh[d], __popc(peers));
        }
    }
    __syncthreads();
    for (int i = tid; i < 2048; i += 256)
        if (sh[i]) atomicAdd(&g_hist1[i], sh[i]);
    __threadfence();
    if (tid == 0) lastFlag = (atomicAdd(&g_done1, 1u) == gridDim.x - 1);
    __syncthreads();
    if (!lastFlag) { pdl_trigger(); return; }

    scan_pick(g_hist1, g_need1, cA, cB, 1, sel1);
    __syncthreads();
    for (int i = tid; i < 2048; i += 256) g_hist1[i] = 0u;
    if (tid == 0) g_done1 = 0u;
    __threadfence();
    pdl_trigger();
}

// ---------------- kernel 3: compact candidates with key >= thresh ----------------
__global__ void __launch_bounds__(256) compact_kernel() {
    pdl_wait();
    unsigned T = g_thresh;
    int lane = threadIdx.x & 31;
    int base = (int)(blockIdx.x * 256u + threadIdx.x) * 4;
    uint4 kv = *(const uint4*)&g_key[base];
    unsigned ks[4] = {kv.x, kv.y, kv.z, kv.w};
#pragma unroll
    for (int e = 0; e < 4; e++) {
        unsigned k = ks[e];
        bool sel = (k >= T);
        unsigned m = __ballot_sync(FULLM, sel);
        if (!m) continue;
        unsigned pos0;
        if (lane == 0) pos0 = atomicAdd(&g_ncand, __popc(m));
        pos0 = __shfl_sync(FULLM, pos0, 0);
        if (sel) {
            unsigned pos = pos0 + __popc(m & ((1u << lane) - 1u));
            if (pos < CAP)
                g_cand[pos] = (((unsigned long long)k) << 32) | (unsigned)(~(unsigned)(base + e));
        }
    }
    __threadfence();
    pdl_trigger();
}

// ---- kernel 4: rank, spread over 48 blocks (1 cand/thread) + prep in last block ----
__global__ void __launch_bounds__(RTHR) rank_kernel(const float* __restrict__ boxes) {
    __shared__ __align__(16) unsigned long long buf[CAP];   // 48000 B
    __shared__ int lastFlag;
    int tid = threadIdx.x;
    pdl_wait();
    unsigned nc = __ldcg(&g_ncand);
    if (nc > CAP) nc = CAP;
    int i = (int)(blockIdx.x * (unsigned)RTHR) + tid;

    if (blockIdx.x * (unsigned)RTHR < nc) {
        for (unsigned j = tid; j < nc; j += RTHR) buf[j] = __ldcg(&g_cand[j]);
        __syncthreads();
        if (i < (int)nc) {
            unsigned long long my = buf[i];
            unsigned r = 0;
            unsigned ncev = nc & ~1u;
            for (unsigned j = 0; j < ncev; j += 2) {           // LDS.128: 2 keys/load
                ulonglong2 p2 = *reinterpret_cast<const ulonglong2*>(&buf[j]);
                r += (p2.x > my) ? 1u : 0u;
                r += (p2.y > my) ? 1u : 0u;
            }
            if (nc & 1u) r += (buf[ncev] > my) ? 1u : 0u;
            if (r < KTOP) g_sorted[r] = my;
        }
    }
    __threadfence();
    if (tid == 0) lastFlag = (atomicAdd(&g_done3, 1u) == gridDim.x - 1);
    __syncthreads();
    if (!lastFlag) { pdl_trigger(); return; }

    // prep: decode sorted list, gather boxes, global max coordinate
    for (int r = tid; r < KTOP; r += RTHR) {
        unsigned long long s = __ldcg(&g_sorted[r]);
        unsigned idx = ~(unsigned)(s & 0xffffffffull);
        unsigned kb = (unsigned)(s >> 32);
        unsigned fb = (kb & 0x80000000u) ? (kb & 0x7fffffffu) : ~kb;
        float4 bx = __ldg((const float4*)boxes + idx);
        g_box[r] = bx;
        g_conf[r] = __uint_as_float(fb);
        g_labf[r] = (float)(unsigned)g_label[idx];
        float m = fmaxf(fmaxf(bx.x, bx.y), fmaxf(bx.z, bx.w));
        atomicMax(&g_maxc, __float_as_uint(m));   // coords >= 0 -> bit-monotone
    }
    if (tid == 0) { g_done3 = 0u; g_ncand = 0u; }
    __threadfence();
    pdl_trigger();
}

// ---------------- kernel 5: IoU mask + final NMS in last block -------------------
__global__ void __launch_bounds__(256) mask_kernel(float* __restrict__ out) {
    __shared__ float4 sobox[KTOP];              // 16 KB
    __shared__ int lastFlag;
    __shared__ unsigned keepw[32], nzm[32];
    __shared__ unsigned short list[KTOP];
    __shared__ int Lsh;
    int tid = threadIdx.x, lane = tid & 31, warp = tid >> 5;

    pdl_wait();
    float mc = __uint_as_float(__ldcg(&g_maxc)) + 1.0f;   // max(top_boxes)+1
    for (int j = tid; j < KTOP; j += 256) {
        float4 b = __ldcg(&g_box[j]);
        float off = __ldcg(&g_labf[j]) * mc;
        sobox[j] = make_float4(b.x + off, b.y + off, b.z + off, b.w + off);
    }
    __syncthreads();

    int row = (int)blockIdx.x * 8 + warp;
    float4 bi = sobox[row];
    float ai = (bi.z - bi.x) * (bi.w - bi.y);
    unsigned rowor = 0;
#pragma unroll 4
    for (int it = 0; it < 32; it++) {
        int j = it * 32 + lane;
        float4 bj = sobox[j];
        float aj = (bj.z - bj.x) * (bj.w - bj.y);
        float lx = fmaxf(bi.x, bj.x), ly = fmaxf(bi.y, bj.y);
        float rx = fminf(bi.z, bj.z), ry = fminf(bi.w, bj.w);
        float w = fmaxf(rx - lx, 0.0f), h = fmaxf(ry - ly, 0.0f);
        float inter = w * h;
        float uni = ai + aj - inter;
        float iou = inter / fmaxf(uni, 1e-9f);
        bool sup = (iou > 0.6f) && (j > row);
        unsigned bal = __ballot_sync(FULLM, sup);
        if (lane == 0) g_mask[row * 32 + it] = bal;
        rowor |= bal;
    }
    if (lane == 0) g_rownz[row] = (rowor != 0u) ? 1 : 0;

    __threadfence();
    if (tid == 0) lastFlag = (atomicAdd(&g_done4, 1u) == gridDim.x - 1);
    __syncthreads();
    if (!lastFlag) { pdl_trigger(); return; }

    // final: sparse greedy NMS + masked output
    for (int w = warp; w < 32; w += 8) {
        float c = __ldcg(&g_conf[w * 32 + lane]);
        unsigned b = __ballot_sync(FULLM, c >= 0.5f);
        if (lane == 0) keepw[w] = b;
    }
    for (int w = warp; w < 32; w += 8) {
        unsigned char z = __ldcg(&g_rownz[w * 32 + lane]);
        unsigned b = __ballot_sync(FULLM, z != 0);
        if (lane == 0) nzm[w] = b;
    }
    __syncthreads();
    if (tid == 0) {
        int L = 0;
        for (int w = 0; w < 32; w++) {
            unsigned m = nzm[w];
            while (m) { int b = __ffs(m) - 1; list[L++] = (unsigned short)(w * 32 + b); m &= m - 1; }
        }
        Lsh = L;
    }
    __syncthreads();
    if (warp == 0) {
        unsigned kw = keepw[lane];
        int L = Lsh;
        for (int t = 0; t < L; t++) {
            int i = list[t];
            unsigned ow = __shfl_sync(FULLM, kw, i >> 5);
            if ((ow >> (i & 31)) & 1u) kw &= ~__ldcg(&g_mask[i * 32 + lane]);
        }
        keepw[lane] = kw;
    }
    __syncthreads();
    for (int r = tid; r < KTOP; r += 256) {
        bool kp = (keepw[r >> 5] >> (r & 31)) & 1u;
        float4 b = __ldcg(&g_box[r]);
        float c = __ldcg(&g_conf[r]);
        float lf = __ldcg(&g_labf[r]);
        float* o = out + r * 6;
        if (kp) { o[0] = b.x; o[1] = b.y; o[2] = b.z; o[3] = b.w; o[4] = c; o[5] = lf; }
        else    { o[0] = 0.f; o[1] = 0.f; o[2] = 0.f; o[3] = 0.f; o[4] = 0.f; o[5] = 0.f; }
    }
    if (tid == 0) { g_done4 = 0u; g_maxc = 0u; }
    __threadfence();
    pdl_trigger();
}

// ------- launch: PDL attribute, with plain-launch fallback if rejected -----------
template <typename K, typename... Args>
static inline void launch_pdl(K kern, dim3 grid, dim3 block, Args... args) {
    cudaLaunchAttribute attr[1];
    attr[0].id = cudaLaunchAttributeProgrammaticStreamSerialization;
    attr[0].val.programmaticStreamSerializationAllowed = 1;
    cudaLaunchConfig_t cfg = {};
    cfg.gridDim = grid;
    cfg.blockDim = block;
    cfg.dynamicSmemBytes = 0;
    cfg.stream = 0;
    cfg.attrs = attr;
    cfg.numAttrs = 1;
    cudaError_t err = cudaLaunchKernelEx(&cfg, kern, args...);
    if (err != cudaSuccess) {
        (void)cudaGetLastError();
        kern<<<grid, block>>>(args...);
    }
}

extern "C" void kernel_launch(void* const* d_in, const int* in_sizes, int n_in,
                              void* d_out, int out_size) {
    const float* boxes  = (const float*)d_in[0];
    const float* scores = (const float*)d_in[1];
    if (n_in >= 2 && in_sizes[0] > in_sizes[1]) { const float* t = boxes; boxes = scores; scores = t; }

    launch_pdl(conf_kernel,    dim3(N_ANCH / 64),   dim3(256), scores);
    launch_pdl(hist_kernel,    dim3(N_ANCH / 1024), dim3(256));
    launch_pdl(compact_kernel, dim3(N_ANCH / 1024), dim3(256));
    launch_pdl(rank_kernel,    dim3(RBLK),          dim3(RTHR), boxes);
    launch_pdl(mask_kernel,    dim3(KTOP / 8),      dim3(256), (float*)d_out);
}

// round 16
// speedup vs baseline: 1.2572x; 1.0525x over previous
#include <cuda_runtime.h>

#define N_ANCH 262144
#define N_CLS 80
#define KTOP 1024
#define CAP 6000
#define RTHR 128
#define RBLK 48
#define FULLM 0xffffffffu

// ---------------- device scratch (zero-initialized at load; reset at end-of-use) ----
__device__ __align__(16) unsigned g_key[N_ANCH];
__device__ unsigned char       g_label[N_ANCH];
__device__ unsigned            g_hist0[2048], g_hist1[2048];
__device__ unsigned            g_done0, g_done1, g_done3, g_done4;
__device__ unsigned            g_sel1, g_need1, g_thresh;
__device__ unsigned            g_ncand, g_maxc;
__device__ __align__(16) unsigned long long g_cand[CAP];
__device__ unsigned long long  g_sorted[KTOP];
__device__ float4              g_box[KTOP];
__device__ float               g_conf[KTOP], g_labf[KTOP];
__device__ unsigned            g_mask[KTOP * 32];
__device__ unsigned char       g_rownz[KTOP];

__device__ __forceinline__ unsigned fkey(float f) {
    unsigned u = __float_as_uint(f);
    return (u & 0x80000000u) ? ~u : (u | 0x80000000u);
}
__device__ __forceinline__ void pdl_wait()    { asm volatile("griddepcontrol.wait;" ::: "memory"); }
__device__ __forceinline__ void pdl_trigger() { asm volatile("griddepcontrol.launch_dependents;" ::: "memory"); }

// Suffix-scan a 2048-bin histogram (256 threads); find the bin where the
// suffix-count crosses `need`. pass0 -> (g_sel1,g_need1); pass1 -> g_thresh.
__device__ __forceinline__ void scan_pick(const unsigned* hist, unsigned need,
                                          unsigned* cA, unsigned* cB, int pass, unsigned sel1) {
    int tid = threadIdx.x;
    unsigned v[8]; unsigned s = 0;
#pragma unroll
    for (int k = 0; k < 8; k++) { v[k] = __ldcg(&hist[tid * 8 + k]); s += v[k]; }
    cA[tid] = s;
    __syncthreads();
    unsigned* a = cA; unsigned* b = cB;
    for (int off = 1; off < 256; off <<= 1) {
        unsigned x = a[tid] + ((tid + off < 256) ? a[tid + off] : 0u);
        b[tid] = x;
        __syncthreads();
        unsigned* t = a; a = b; b = t;
    }
    unsigned Cexcl = (tid + 1 < 256) ? a[tid + 1] : 0u;
    unsigned Sincl[8];
    unsigned run = Cexcl;
    for (int k = 7; k >= 0; k--) { run += v[k]; Sincl[k] = run; }
#pragma unroll
    for (int k = 0; k < 8; k++) {
        unsigned Sx = (k < 7) ? Sincl[k + 1] : Cexcl;
        if (Sx < need && need <= Sincl[k]) {
            unsigned bin = (unsigned)(tid * 8 + k);
            if (pass == 0) { g_sel1 = bin; g_need1 = need - Sx; }
            else           { g_thresh = (sel1 << 21) | (bin << 10); }
        }
    }
}

// ---------------- kernel 1: conf/argmax + fused hist pass 0 ----------------
__global__ void __launch_bounds__(256) conf_kernel(const float* __restrict__ scores) {
    __shared__ unsigned sh[2048];
    __shared__ unsigned cA[256], cB[256];
    __shared__ int lastFlag;
    int tid = threadIdx.x, lane = tid & 31;
    for (int i = tid; i < 2048; i += 256) sh[i] = 0u;

    int gw = (int)((blockIdx.x * 256u + tid) >> 5);
    int g = lane >> 2, c = lane & 3;
    int anchor = gw * 8 + g;
    const float4* p = (const float4*)scores + (size_t)anchor * 20;
    float4 f0 = __ldg(p + c);
    float4 f1 = __ldg(p + c + 4);
    float4 f2 = __ldg(p + c + 8);
    float4 f3 = __ldg(p + c + 12);
    float4 f4 = __ldg(p + c + 16);

    unsigned long long best = 0ull;
#define UPD(val, idx) { unsigned long long k64 = ((unsigned long long)__float_as_uint(val) << 32) \
                                               | (unsigned)(~(unsigned)(idx)); if (k64 > best) best = k64; }
    int b0 = 4 * c;
    UPD(f0.x, b0 + 0)  UPD(f0.y, b0 + 1)  UPD(f0.z, b0 + 2)  UPD(f0.w, b0 + 3)
    UPD(f1.x, b0 + 16) UPD(f1.y, b0 + 17) UPD(f1.z, b0 + 18) UPD(f1.w, b0 + 19)
    UPD(f2.x, b0 + 32) UPD(f2.y, b0 + 33) UPD(f2.z, b0 + 34) UPD(f2.w, b0 + 35)
    UPD(f3.x, b0 + 48) UPD(f3.y, b0 + 49) UPD(f3.z, b0 + 50) UPD(f3.w, b0 + 51)
    UPD(f4.x, b0 + 64) UPD(f4.y, b0 + 65) UPD(f4.z, b0 + 66) UPD(f4.w, b0 + 67)
#undef UPD
    unsigned long long o;
    o = __shfl_xor_sync(FULLM, best, 1); if (o > best) best = o;
    o = __shfl_xor_sync(FULLM, best, 2); if (o > best) best = o;

    unsigned key = 0;
    bool act = (c == 0);
    if (act) {
        unsigned bits = (unsigned)(best >> 32);
        unsigned label = ~(unsigned)(best & 0xffffffffull);
        float conf = __uint_as_float(bits);
        float mk = (conf >= 0.5f) ? conf : -1.0f;
        key = fkey(mk);
        g_key[anchor] = key;
        g_label[anchor] = (unsigned char)label;
    }
    unsigned am = __ballot_sync(FULLM, act);
    if (act) {
        unsigned d = key >> 21;
        unsigned peers = __match_any_sync(am, d);
        if ((unsigned)(__ffs(peers) - 1) == (unsigned)lane) atomicAdd(&sh[d], __popc(peers));
    }
    __syncthreads();
    for (int i = tid; i < 2048; i += 256)
        if (sh[i]) atomicAdd(&g_hist0[i], sh[i]);
    __threadfence();
    if (tid == 0) lastFlag = (atomicAdd(&g_done0, 1u) == gridDim.x - 1);
    __syncthreads();
    if (!lastFlag) { pdl_trigger(); return; }

    scan_pick(g_hist0, KTOP, cA, cB, 0, 0);
    __syncthreads();
    for (int i = tid; i < 2048; i += 256) g_hist0[i] = 0u;
    if (tid == 0) g_done0 = 0u;
    __threadfence();
    pdl_trigger();
}

// ---------------- kernel 2: radix pass 1 -> threshold ----------------
__global__ void __launch_bounds__(256) hist_kernel() {
    __shared__ unsigned sh[2048];
    __shared__ unsigned cA[256], cB[256];
    __shared__ int lastFlag;
    int tid = threadIdx.x, lane = tid & 31;
    for (int i = tid; i < 2048; i += 256) sh[i] = 0u;
    __syncthreads();
    pdl_wait();
    unsigned sel1 = g_sel1;

    int base = (int)(blockIdx.x * 256u + tid) * 4;
    uint4 kv = *(const uint4*)&g_key[base];
    unsigned ks[4] = {kv.x, kv.y, kv.z, kv.w};
#pragma unroll
    for (int e = 0; e < 4; e++) {
        unsigned k = ks[e];
        bool act = ((k >> 21) == sel1);
        unsigned d = (k >> 10) & 2047u;
        unsigned am = __ballot_sync(FULLM, act);
        if (act) {
            unsigned peers = __match_any_sync(am, d);
            if ((unsigned)(__ffs(peers) - 1) == (unsigned)lane) atomicAdd(&sh[d], __popc(peers));
        }
    }
    __syncthreads();
    for (int i = tid; i < 2048; i += 256)
        if (sh[i]) atomicAdd(&g_hist1[i], sh[i]);
    __threadfence();
    if (tid == 0) lastFlag = (atomicAdd(&g_done1, 1u) == gridDim.x - 1);
    __syncthreads();
    if (!lastFlag) { pdl_trigger(); return; }

    scan_pick(g_hist1, g_need1, cA, cB, 1, sel1);
    __syncthreads();
    for (int i = tid; i < 2048; i += 256) g_hist1[i] = 0u;
    if (tid == 0) g_done1 = 0u;
    __threadfence();
    pdl_trigger();
}

// ---------------- kernel 3: compact candidates with key >= thresh ----------------
__global__ void __launch_bounds__(256) compact_kernel() {
    pdl_wait();
    unsigned T = g_thresh;
    int lane = threadIdx.x & 31;
    int base = (int)(blockIdx.x * 256u + threadIdx.x) * 4;
    uint4 kv = *(const uint4*)&g_key[base];
    unsigned ks[4] = {kv.x, kv.y, kv.z, kv.w};
#pragma unroll
    for (int e = 0; e < 4; e++) {
        unsigned k = ks[e];
        bool sel = (k >= T);
        unsigned m = __ballot_sync(FULLM, sel);
        if (!m) continue;
        unsigned pos0;
        if (lane == 0) pos0 = atomicAdd(&g_ncand, __popc(m));
        pos0 = __shfl_sync(FULLM, pos0, 0);
        if (sel) {
            unsigned pos = pos0 + __popc(m & ((1u << lane) - 1u));
            if (pos < CAP)
                g_cand[pos] = (((unsigned long long)k) << 32) | (unsigned)(~(unsigned)(base + e));
        }
    }
    __threadfence();
    pdl_trigger();
}

// ---- kernel 4: rank with MLP=4 unrolled count loop + prep in last block ---------
__global__ void __launch_bounds__(RTHR) rank_kernel(const float* __restrict__ boxes) {
    __shared__ __align__(16) unsigned long long buf[CAP];   // 48000 B
    __shared__ int lastFlag;
    int tid = threadIdx.x;
    pdl_wait();
    unsigned nc = __ldcg(&g_ncand);
    if (nc > CAP) nc = CAP;
    int i = (int)(blockIdx.x * (unsigned)RTHR) + tid;

    if (blockIdx.x * (unsigned)RTHR < nc) {
        for (unsigned j = tid; j < nc; j += RTHR) buf[j] = __ldcg(&g_cand[j]);
        __syncthreads();
        if (i < (int)nc) {
            unsigned long long my = buf[i];
            unsigned r = 0;
            unsigned j = 0;
            // 8 keys per iteration: 4 independent LDS.128 in flight (hide 29-cy LDS lat)
            for (; j + 8 <= nc; j += 8) {
                ulonglong2 q0 = *reinterpret_cast<const ulonglong2*>(&buf[j + 0]);
                ulonglong2 q1 = *reinterpret_cast<const ulonglong2*>(&buf[j + 2]);
                ulonglong2 q2 = *reinterpret_cast<const ulonglong2*>(&buf[j + 4]);
                ulonglong2 q3 = *reinterpret_cast<const ulonglong2*>(&buf[j + 6]);
                unsigned a0 = (q0.x > my) ? 1u : 0u;
                unsigned a1 = (q0.y > my) ? 1u : 0u;
                unsigned a2 = (q1.x > my) ? 1u : 0u;
                unsigned a3 = (q1.y > my) ? 1u : 0u;
                unsigned a4 = (q2.x > my) ? 1u : 0u;
                unsigned a5 = (q2.y > my) ? 1u : 0u;
                unsigned a6 = (q3.x > my) ? 1u : 0u;
                unsigned a7 = (q3.y > my) ? 1u : 0u;
                r += ((a0 + a1) + (a2 + a3)) + ((a4 + a5) + (a6 + a7));
            }
            for (; j < nc; j++) r += (buf[j] > my) ? 1u : 0u;
            if (r < KTOP) g_sorted[r] = my;
        }
    }
    __threadfence();
    if (tid == 0) lastFlag = (atomicAdd(&g_done3, 1u) == gridDim.x - 1);
    __syncthreads();
    if (!lastFlag) { pdl_trigger(); return; }

    // prep: decode sorted list, gather boxes, global max coordinate
    for (int r = tid; r < KTOP; r += RTHR) {
        unsigned long long s = __ldcg(&g_sorted[r]);
        unsigned idx = ~(unsigned)(s & 0xffffffffull);
        unsigned kb = (unsigned)(s >> 32);
        unsigned fb = (kb & 0x80000000u) ? (kb & 0x7fffffffu) : ~kb;
        float4 bx = __ldg((const float4*)boxes + idx);
        g_box[r] = bx;
        g_conf[r] = __uint_as_float(fb);
        g_labf[r] = (float)(unsigned)g_label[idx];
        float m = fmaxf(fmaxf(bx.x, bx.y), fmaxf(bx.z, bx.w));
        atomicMax(&g_maxc, __float_as_uint(m));   // coords >= 0 -> bit-monotone
    }
    if (tid == 0) { g_done3 = 0u; g_ncand = 0u; }
    __threadfence();
    pdl_trigger();
}

// ---------------- kernel 5: IoU mask + final NMS in last block -------------------
__global__ void __launch_bounds__(256) mask_kernel(float* __restrict__ out) {
    __shared__ float4 sobox[KTOP];              // 16 KB
    __shared__ int lastFlag;
    __shared__ unsigned keepw[32], nzm[32];
    __shared__ unsigned short list[KTOP];
    __shared__ int Lsh;
    int tid = threadIdx.x, lane = tid & 31, warp = tid >> 5;

    pdl_wait();
    float mc = __uint_as_float(__ldcg(&g_maxc)) + 1.0f;   // max(top_boxes)+1
    for (int j = tid; j < KTOP; j += 256) {
        float4 b = __ldcg(&g_box[j]);
        float off = __ldcg(&g_labf[j]) * mc;
        sobox[j] = make_float4(b.x + off, b.y + off, b.z + off, b.w + off);
    }
    __syncthreads();

    int row = (int)blockIdx.x * 8 + warp;
    float4 bi = sobox[row];
    float ai = (bi.z - bi.x) * (bi.w - bi.y);
    unsigned rowor = 0;
#pragma unroll 4
    for (int it = 0; it < 32; it++) {
        int j = it * 32 + lane;
        float4 bj = sobox[j];
        float aj = (bj.z - bj.x) * (bj.w - bj.y);
        float lx = fmaxf(bi.x, bj.x), ly = fmaxf(bi.y, bj.y);
        float rx = fminf(bi.z, bj.z), ry = fminf(bi.w, bj.w);
        float w = fmaxf(rx - lx, 0.0f), h = fmaxf(ry - ly, 0.0f);
        float inter = w * h;
        float uni = ai + aj - inter;
        float iou = inter / fmaxf(uni, 1e-9f);
        bool sup = (iou > 0.6f) && (j > row);
        unsigned bal = __ballot_sync(FULLM, sup);
        if (lane == 0) g_mask[row * 32 + it] = bal;
        rowor |= bal;
    }
    if (lane == 0) g_rownz[row] = (rowor != 0u) ? 1 : 0;

    __threadfence();
    if (tid == 0) lastFlag = (atomicAdd(&g_done4, 1u) == gridDim.x - 1);
    __syncthreads();
    if (!lastFlag) { pdl_trigger(); return; }

    // final: sparse greedy NMS + masked output
    for (int w = warp; w < 32; w += 8) {
        float c = __ldcg(&g_conf[w * 32 + lane]);
        unsigned b = __ballot_sync(FULLM, c >= 0.5f);
        if (lane == 0) keepw[w] = b;
    }
    for (int w = warp; w < 32; w += 8) {
        unsigned char z = __ldcg(&g_rownz[w * 32 + lane]);
        unsigned b = __ballot_sync(FULLM, z != 0);
        if (lane == 0) nzm[w] = b;
    }
    __syncthreads();
    if (tid == 0) {
        int L = 0;
        for (int w = 0; w < 32; w++) {
            unsigned m = nzm[w];
            while (m) { int b = __ffs(m) - 1; list[L++] = (unsigned short)(w * 32 + b); m &= m - 1; }
        }
        Lsh = L;
    }
    __syncthreads();
    if (warp == 0) {
        unsigned kw = keepw[lane];
        int L = Lsh;
        for (int t = 0; t < L; t++) {
            int i = list[t];
            unsigned ow = __shfl_sync(FULLM, kw, i >> 5);
            if ((ow >> (i & 31)) & 1u) kw &= ~__ldcg(&g_mask[i * 32 + lane]);
        }
        keepw[lane] = kw;
    }
    __syncthreads();
    for (int r = tid; r < KTOP; r += 256) {
        bool kp = (keepw[r >> 5] >> (r & 31)) & 1u;
        float4 b = __ldcg(&g_box[r]);
        float c = __ldcg(&g_conf[r]);
        float lf = __ldcg(&g_labf[r]);
        float* o = out + r * 6;
        if (kp) { o[0] = b.x; o[1] = b.y; o[2] = b.z; o[3] = b.w; o[4] = c; o[5] = lf; }
        else    { o[0] = 0.f; o[1] = 0.f; o[2] = 0.f; o[3] = 0.f; o[4] = 0.f; o[5] = 0.f; }
    }
    if (tid == 0) { g_done4 = 0u; g_maxc = 0u; }
    __threadfence();
    pdl_trigger();
}

// ------- launch: PDL attribute, with plain-launch fallback if rejected -----------
template <typename K, typename... Args>
static inline void launch_pdl(K kern, dim3 grid, dim3 block, Args... args) {
    cudaLaunchAttribute attr[1];
    attr[0].id = cudaLaunchAttributeProgrammaticStreamSerialization;
    attr[0].val.programmaticStreamSerializationAllowed = 1;
    cudaLaunchConfig_t cfg = {};
    cfg.gridDim = grid;
    cfg.blockDim = block;
    cfg.dynamicSmemBytes = 0;
    cfg.stream = 0;
    cfg.attrs = attr;
    cfg.numAttrs = 1;
    cudaError_t err = cudaLaunchKernelEx(&cfg, kern, args...);
    if (err != cudaSuccess) {
        (void)cudaGetLastError();
        kern<<<grid, block>>>(args...);
    }
}

extern "C" void kernel_launch(void* const* d_in, const int* in_sizes, int n_in,
                              void* d_out, int out_size) {
    const float* boxes  = (const float*)d_in[0];
    const float* scores = (const float*)d_in[1];
    if (n_in >= 2 && in_sizes[0] > in_sizes[1]) { const float* t = boxes; boxes = scores; scores = t; }

    launch_pdl(conf_kernel,    dim3(N_ANCH / 64),   dim3(256), scores);
    launch_pdl(hist_kernel,    dim3(N_ANCH / 1024), dim3(256));
    launch_pdl(compact_kernel, dim3(N_ANCH / 1024), dim3(256));
    launch_pdl(rank_kernel,    dim3(RBLK),          dim3(RTHR), boxes);
    launch_pdl(mask_kernel,    dim3(KTOP / 8),      dim3(256), (float*)d_out);
}